// round 16
// baseline (speedup 1.0000x reference)
#include <cuda_runtime.h>
#include <cuda_fp16.h>

// Triline interpolation, fp16 packed (base,diff) tables + packed fp16 math.
//   out[b, :] = lerp(x_line, cx) + lerp(y_line, cy) + lerp(z_line, cz)
// B = 1M, C = 64, N = 512.
//
// SMEM entry per lane per row: uint4 {h2(b0,b1), h2(b2,b3), h2(d0,d1), h2(d2,d3)}
// (channel-pair packing). Consume = 6 HFMA2 + 4 HADD2 + 4 cvt: ~40% fewer
// issues than the scalar fp32 version. One row read per table per point
// (3 LDS.128), conflict-free 128 B rows. Each CTA owns a 32-channel half of
// all three tables: 192 KB -> 1 CTA/SM.

#define N_ROWS  512
#define C_CH    64
#define CHALF   32
#define NCHUNK  148
#define BLOCK   1024
#define PTS_IT  (BLOCK / 8)                       // 128 points per CTA-iteration
#define TBL_U4  (N_ROWS * 8)                      // 4096 uint4 per table
#define SMEM_BYTES (3 * TBL_U4 * 16)              // 192 KB

__global__ __launch_bounds__(BLOCK, 1) void triline_pk_kernel(
    const float* __restrict__ coords,   // [B, 3]
    const float* __restrict__ x_line,   // [N, C] fp32
    const float* __restrict__ y_line,
    const float* __restrict__ z_line,
    const float* __restrict__ grid,     // [N]
    float* __restrict__ out,            // [B, C] fp32
    int B, int ptsPer)
{
    extern __shared__ uint4 smu4[];     // [3][512][8] of packed lanes
    uint4* sx = smu4;
    uint4* sy = smu4 + TBL_U4;
    uint4* sz = smu4 + 2 * TBL_U4;

    const int tIn   = threadIdx.x;
    const int half  = blockIdx.x & 1;          // channel half: 0 or 1
    const int chunk = blockIdx.x >> 1;         // point chunk: 0..147
    const int choff = half * CHALF;

    // ---- Stage packed (base, diff) for this channel-half of the tables ----
    for (int i = tIn; i < TBL_U4; i += BLOCK) {
        const int row  = i >> 3;               // source row
        const int q    = (i & 7) << 2;         // 4-channel group within half
        const int rown = min(row + 1, N_ROWS - 1);
        const int s0   = row  * C_CH + choff + q;
        const int s1   = rown * C_CH + choff + q;

        const float4 x0 = *(const float4*)(x_line + s0);
        const float4 x1 = *(const float4*)(x_line + s1);
        const float4 y0 = *(const float4*)(y_line + s0);
        const float4 y1 = *(const float4*)(y_line + s1);
        const float4 z0 = *(const float4*)(z_line + s0);
        const float4 z1 = *(const float4*)(z_line + s1);

        uint4 px, py, pz;
        *(__half2*)&px.x = __floats2half2_rn(x0.x, x0.y);
        *(__half2*)&px.y = __floats2half2_rn(x0.z, x0.w);
        *(__half2*)&px.z = __floats2half2_rn(x1.x - x0.x, x1.y - x0.y);
        *(__half2*)&px.w = __floats2half2_rn(x1.z - x0.z, x1.w - x0.w);
        *(__half2*)&py.x = __floats2half2_rn(y0.x, y0.y);
        *(__half2*)&py.y = __floats2half2_rn(y0.z, y0.w);
        *(__half2*)&py.z = __floats2half2_rn(y1.x - y0.x, y1.y - y0.y);
        *(__half2*)&py.w = __floats2half2_rn(y1.z - y0.z, y1.w - y0.w);
        *(__half2*)&pz.x = __floats2half2_rn(z0.x, z0.y);
        *(__half2*)&pz.y = __floats2half2_rn(z0.z, z0.w);
        *(__half2*)&pz.z = __floats2half2_rn(z1.x - z0.x, z1.y - z0.y);
        *(__half2*)&pz.w = __floats2half2_rn(z1.z - z0.z, z1.w - z0.w);

        sx[i] = px;  sy[i] = py;  sz[i] = pz;
    }

    const float g0    = __ldg(grid);
    const float invdx = 1.0f / (__ldg(grid + 1) - g0);

    __syncthreads();

    const int lane8  = tIn & 7;                // uint4 slot within the row
    const int pstart = chunk * ptsPer;
    const int pend   = min(pstart + ptsPer, B);

    int p = pstart + (tIn >> 3);
    if (p >= pend) return;

    // ---- Prologue: indices/weights for the first point ----
    int ix, iy, iz;  float wx, wy, wz;
    {
        const float cx = __ldg(coords + 3 * p + 0);
        const float cy = __ldg(coords + 3 * p + 1);
        const float cz = __ldg(coords + 3 * p + 2);
        const float px = (cx - g0) * invdx;
        const float py = (cy - g0) * invdx;
        const float pz = (cz - g0) * invdx;
        ix = min(max(__float2int_rd(px), 0), N_ROWS - 2);
        iy = min(max(__float2int_rd(py), 0), N_ROWS - 2);
        iz = min(max(__float2int_rd(pz), 0), N_ROWS - 2);
        wx = px - (float)ix;  wy = py - (float)iy;  wz = pz - (float)iz;
    }

    for (; p < pend; ) {
        // ---- 3 conflict-free LDS.128 ----
        const uint4 ux = sx[(ix << 3) + lane8];
        const uint4 uy = sy[(iy << 3) + lane8];
        const uint4 uz = sz[(iz << 3) + lane8];

        const __half2 wx2 = __float2half2_rn(wx);
        const __half2 wy2 = __float2half2_rn(wy);
        const __half2 wz2 = __float2half2_rn(wz);

        // ---- Prefetch next point's coords + index math (fills LDS shadow) ----
        const int pn = p + PTS_IT;
        const int pl = (pn < pend) ? pn : p;
        const float cx = __ldg(coords + 3 * pl + 0);
        const float cy = __ldg(coords + 3 * pl + 1);
        const float cz = __ldg(coords + 3 * pl + 2);
        const float px = (cx - g0) * invdx;
        const float py = (cy - g0) * invdx;
        const float pz = (cz - g0) * invdx;
        const int nix = min(max(__float2int_rd(px), 0), N_ROWS - 2);
        const int niy = min(max(__float2int_rd(py), 0), N_ROWS - 2);
        const int niz = min(max(__float2int_rd(pz), 0), N_ROWS - 2);
        const float nwx = px - (float)nix;
        const float nwy = py - (float)niy;
        const float nwz = pz - (float)niz;

        // ---- Consume: packed fp16 lerp + fp16 cross-line sum ----
        const __half2 lx01 = __hfma2(wx2, *(const __half2*)&ux.z, *(const __half2*)&ux.x);
        const __half2 lx23 = __hfma2(wx2, *(const __half2*)&ux.w, *(const __half2*)&ux.y);
        const __half2 ly01 = __hfma2(wy2, *(const __half2*)&uy.z, *(const __half2*)&uy.x);
        const __half2 ly23 = __hfma2(wy2, *(const __half2*)&uy.w, *(const __half2*)&uy.y);
        const __half2 lz01 = __hfma2(wz2, *(const __half2*)&uz.z, *(const __half2*)&uz.x);
        const __half2 lz23 = __hfma2(wz2, *(const __half2*)&uz.w, *(const __half2*)&uz.y);

        const __half2 s01 = __hadd2(__hadd2(lx01, ly01), lz01);
        const __half2 s23 = __hadd2(__hadd2(lx23, ly23), lz23);

        const float2 f01 = __half22float2(s01);
        const float2 f23 = __half22float2(s23);

        float4 r;
        r.x = f01.x;  r.y = f01.y;  r.z = f23.x;  r.w = f23.y;
        *(float4*)(out + (size_t)p * C_CH + choff + (lane8 << 2)) = r;

        // ---- Rotate pipeline state ----
        p = pn;
        ix = nix; iy = niy; iz = niz;
        wx = nwx; wy = nwy; wz = nwz;
    }
}

extern "C" void kernel_launch(void* const* d_in, const int* in_sizes, int n_in,
                              void* d_out, int out_size)
{
    const float* coords = (const float*)d_in[0];
    const float* x_line = (const float*)d_in[1];
    const float* y_line = (const float*)d_in[2];
    const float* z_line = (const float*)d_in[3];
    const float* grid   = (const float*)d_in[4];
    float* out = (float*)d_out;

    const int B = in_sizes[0] / 3;                 // 1048576
    const int ptsPer = (B + NCHUNK - 1) / NCHUNK;  // 7086

    static int smem_set = 0;
    if (!smem_set) {
        cudaFuncSetAttribute(triline_pk_kernel,
                             cudaFuncAttributeMaxDynamicSharedMemorySize, SMEM_BYTES);
        smem_set = 1;
    }

    triline_pk_kernel<<<2 * NCHUNK, BLOCK, SMEM_BYTES>>>(
        coords, x_line, y_line, z_line, grid, out, B, ptsPer);
}

// round 17
// speedup vs baseline: 1.0332x; 1.0332x over previous
#include <cuda_runtime.h>
#include <cuda_fp16.h>

// Triline interpolation, fp16 SMEM tables, LDS double-buffered pipeline.
//   out[b, :] = lerp(x_line, cx) + lerp(y_line, cy) + lerp(z_line, cz)
// B = 1M, C = 64, N = 512.
//
// Grid = 148 CTAs (one point-chunk each), all 64 channels per CTA:
// tables in SMEM as fp16, 192 KB -> 1 CTA/SM, coords read exactly once.
// 16 lanes per point, each lane owns 4 channels (8 B per row -> LDS.64,
// 2 conflict-free phases per warp instruction).
// Pipeline: the 6 gathers for point p+S issue at the TOP of the iteration;
// coords load + index math + consume/store of point p fill the LDS shadow.

#define N_ROWS  512
#define C_CH    64
#define NCHUNK  148
#define BLOCK   1024
#define LANES   16
#define PTS_IT  (BLOCK / LANES)                   // 64 points per CTA-iteration
#define TBL_HALVES (N_ROWS * C_CH)                // 32768 halves per table
#define SMEM_BYTES (3 * TBL_HALVES * 2)           // 192 KB

__global__ __launch_bounds__(BLOCK, 1) void triline_dbuf_kernel(
    const float* __restrict__ coords,   // [B, 3]
    const float* __restrict__ x_line,   // [N, C] fp32
    const float* __restrict__ y_line,
    const float* __restrict__ z_line,
    const float* __restrict__ grid,     // [N]
    float* __restrict__ out,            // [B, C] fp32
    int B, int ptsPer)
{
    extern __shared__ __half smh[];     // [3][512][64]
    __half* sx = smh;
    __half* sy = smh + TBL_HALVES;
    __half* sz = smh + 2 * TBL_HALVES;

    const int tIn = threadIdx.x;

    // ---- Stage all three tables, fp32 -> fp16 ----
    for (int i = tIn; i < TBL_HALVES / 4; i += BLOCK) {
        float4 vx = *(const float4*)(x_line + 4 * i);
        float4 vy = *(const float4*)(y_line + 4 * i);
        float4 vz = *(const float4*)(z_line + 4 * i);
        ((__half2*)sx)[2 * i]     = __floats2half2_rn(vx.x, vx.y);
        ((__half2*)sx)[2 * i + 1] = __floats2half2_rn(vx.z, vx.w);
        ((__half2*)sy)[2 * i]     = __floats2half2_rn(vy.x, vy.y);
        ((__half2*)sy)[2 * i + 1] = __floats2half2_rn(vy.z, vy.w);
        ((__half2*)sz)[2 * i]     = __floats2half2_rn(vz.x, vz.y);
        ((__half2*)sz)[2 * i + 1] = __floats2half2_rn(vz.z, vz.w);
    }

    const float g0    = __ldg(grid);
    const float invdx = 1.0f / (__ldg(grid + 1) - g0);

    __syncthreads();

    const int hoff   = (tIn & (LANES - 1)) << 2;  // 4 half-channels per lane
    const int pstart = blockIdx.x * ptsPer;
    const int pend   = min(pstart + ptsPer, B);

    int p = pstart + (tIn >> 4);
    if (p >= pend) return;
    const int pmax = pend - 1;

    // ---- Prologue ----
    // indices/weights for p, then issue p's gathers; indices/weights for p+S.
    int ix, iy, iz;  float wx, wy, wz;
    {
        const float cx = __ldg(coords + 3 * p + 0);
        const float cy = __ldg(coords + 3 * p + 1);
        const float cz = __ldg(coords + 3 * p + 2);
        const float px = (cx - g0) * invdx;
        const float py = (cy - g0) * invdx;
        const float pz = (cz - g0) * invdx;
        ix = min(max(__float2int_rd(px), 0), N_ROWS - 2);
        iy = min(max(__float2int_rd(py), 0), N_ROWS - 2);
        iz = min(max(__float2int_rd(pz), 0), N_ROWS - 2);
        wx = px - (float)ix;  wy = py - (float)iy;  wz = pz - (float)iz;
    }

    // Current point's gather data (double buffer "front").
    uint2 ux0 = *(const uint2*)(sx + (ix << 6) + hoff);
    uint2 ux1 = *(const uint2*)(sx + ((ix + 1) << 6) + hoff);
    uint2 uy0 = *(const uint2*)(sy + (iy << 6) + hoff);
    uint2 uy1 = *(const uint2*)(sy + ((iy + 1) << 6) + hoff);
    uint2 uz0 = *(const uint2*)(sz + (iz << 6) + hoff);
    uint2 uz1 = *(const uint2*)(sz + ((iz + 1) << 6) + hoff);

    // Indices/weights for p+S.
    int jx, jy, jz;  float vx, vy, vz;
    {
        const int p1 = min(p + PTS_IT, pmax);
        const float cx = __ldg(coords + 3 * p1 + 0);
        const float cy = __ldg(coords + 3 * p1 + 1);
        const float cz = __ldg(coords + 3 * p1 + 2);
        const float px = (cx - g0) * invdx;
        const float py = (cy - g0) * invdx;
        const float pz = (cz - g0) * invdx;
        jx = min(max(__float2int_rd(px), 0), N_ROWS - 2);
        jy = min(max(__float2int_rd(py), 0), N_ROWS - 2);
        jz = min(max(__float2int_rd(pz), 0), N_ROWS - 2);
        vx = px - (float)jx;  vy = py - (float)jy;  vz = pz - (float)jz;
    }

    for (; p < pend; ) {
        // ---- Issue NEXT point's 6 gathers (back buffer) ----
        const uint2 nx0 = *(const uint2*)(sx + (jx << 6) + hoff);
        const uint2 nx1 = *(const uint2*)(sx + ((jx + 1) << 6) + hoff);
        const uint2 ny0 = *(const uint2*)(sy + (jy << 6) + hoff);
        const uint2 ny1 = *(const uint2*)(sy + ((jy + 1) << 6) + hoff);
        const uint2 nz0 = *(const uint2*)(sz + (jz << 6) + hoff);
        const uint2 nz1 = *(const uint2*)(sz + ((jz + 1) << 6) + hoff);

        // ---- Coords LDG + index math for p+2S (covers LDS latency) ----
        const int pf = min(p + 2 * PTS_IT, pmax);
        const float cx = __ldg(coords + 3 * pf + 0);
        const float cy = __ldg(coords + 3 * pf + 1);
        const float cz = __ldg(coords + 3 * pf + 2);
        const float px = (cx - g0) * invdx;
        const float py = (cy - g0) * invdx;
        const float pz = (cz - g0) * invdx;
        const int fix = min(max(__float2int_rd(px), 0), N_ROWS - 2);
        const int fiy = min(max(__float2int_rd(py), 0), N_ROWS - 2);
        const int fiz = min(max(__float2int_rd(pz), 0), N_ROWS - 2);
        const float fwx = px - (float)fix;
        const float fwy = py - (float)fiy;
        const float fwz = pz - (float)fiz;

        // ---- Consume CURRENT point's data (loaded last iteration) ----
        const __half2 wx2 = __float2half2_rn(wx);
        const __half2 wy2 = __float2half2_rn(wy);
        const __half2 wz2 = __float2half2_rn(wz);

        const __half2 x0a = *(const __half2*)&ux0.x, x0b = *(const __half2*)&ux0.y;
        const __half2 x1a = *(const __half2*)&ux1.x, x1b = *(const __half2*)&ux1.y;
        const __half2 y0a = *(const __half2*)&uy0.x, y0b = *(const __half2*)&uy0.y;
        const __half2 y1a = *(const __half2*)&uy1.x, y1b = *(const __half2*)&uy1.y;
        const __half2 z0a = *(const __half2*)&uz0.x, z0b = *(const __half2*)&uz0.y;
        const __half2 z1a = *(const __half2*)&uz1.x, z1b = *(const __half2*)&uz1.y;

        const __half2 lxa = __hfma2(wx2, __hsub2(x1a, x0a), x0a);
        const __half2 lxb = __hfma2(wx2, __hsub2(x1b, x0b), x0b);
        const __half2 lya = __hfma2(wy2, __hsub2(y1a, y0a), y0a);
        const __half2 lyb = __hfma2(wy2, __hsub2(y1b, y0b), y0b);
        const __half2 lza = __hfma2(wz2, __hsub2(z1a, z0a), z0a);
        const __half2 lzb = __hfma2(wz2, __hsub2(z1b, z0b), z0b);

        const float2 fa = __half22float2(lxa), ga = __half22float2(lya), ha = __half22float2(lza);
        const float2 fb = __half22float2(lxb), gb = __half22float2(lyb), hb = __half22float2(lzb);

        float4 r;
        r.x = fa.x + ga.x + ha.x;
        r.y = fa.y + ga.y + ha.y;
        r.z = fb.x + gb.x + hb.x;
        r.w = fb.y + gb.y + hb.y;
        *(float4*)(out + (size_t)p * C_CH + hoff) = r;

        // ---- Rotate pipeline state ----
        p += PTS_IT;
        ux0 = nx0; ux1 = nx1; uy0 = ny0; uy1 = ny1; uz0 = nz0; uz1 = nz1;
        wx = vx; wy = vy; wz = vz;
        jx = fix; jy = fiy; jz = fiz;
        vx = fwx; vy = fwy; vz = fwz;
    }
}

extern "C" void kernel_launch(void* const* d_in, const int* in_sizes, int n_in,
                              void* d_out, int out_size)
{
    const float* coords = (const float*)d_in[0];
    const float* x_line = (const float*)d_in[1];
    const float* y_line = (const float*)d_in[2];
    const float* z_line = (const float*)d_in[3];
    const float* grid   = (const float*)d_in[4];
    float* out = (float*)d_out;

    const int B = in_sizes[0] / 3;                 // 1048576
    const int ptsPer = (B + NCHUNK - 1) / NCHUNK;  // 7086

    static int smem_set = 0;
    if (!smem_set) {
        cudaFuncSetAttribute(triline_dbuf_kernel,
                             cudaFuncAttributeMaxDynamicSharedMemorySize, SMEM_BYTES);
        smem_set = 1;
    }

    triline_dbuf_kernel<<<NCHUNK, BLOCK, SMEM_BYTES>>>(
        coords, x_line, y_line, z_line, grid, out, B, ptsPer);
}